// round 16
// baseline (speedup 1.0000x reference)
#include <cuda_runtime.h>
#include <cuda_fp16.h>
#include <math.h>
#include <stdint.h>

#define HW 65536

// ---------------- device scratch ----------------
__device__ float  g_w2c[8 * 16];
__device__ int    g_idx[16 * HW];
__device__ int    g_cnt[16];
__device__ __half g_wB[2 * 2 * 9 * 32 * 64]; // [conv][coh][tap][col32][64ci] swizzled fp16
__device__ __half g_fused[8ll * HW * 64];    // NHWC fp16
__device__ __half g_mid[8ll * HW * 64];      // NHWC fp16

__constant__ int c_pj[6] = {0, 1, 1, 2, 2, 3};
__constant__ int c_pk[6] = {1, 0, 2, 1, 3, 2};

__device__ __forceinline__ uint32_t smem_u32(const void* p) {
    uint32_t a;
    asm("{ .reg .u64 t; cvta.to.shared.u64 t, %1; cvt.u32.u64 %0, t; }" : "=r"(a) : "l"(p));
    return a;
}
__device__ __forceinline__ uint32_t f22h(float a, float b) {
    __half2 h = __floats2half2_rn(a, b);
    return *reinterpret_cast<uint32_t*>(&h);
}
__device__ __forceinline__ void mma_f16(float* d, const uint32_t* a, const uint32_t* b) {
    asm volatile(
        "mma.sync.aligned.m16n8k16.row.col.f32.f16.f16.f32 "
        "{%0,%1,%2,%3}, {%4,%5,%6,%7}, {%8,%9}, {%0,%1,%2,%3};"
        : "+f"(d[0]), "+f"(d[1]), "+f"(d[2]), "+f"(d[3])
        : "r"(a[0]), "r"(a[1]), "r"(a[2]), "r"(a[3]), "r"(b[0]), "r"(b[1]));
}
__device__ __forceinline__ void ldsm4(uint32_t* r, uint32_t addr) {
    asm volatile("ldmatrix.sync.aligned.m8n8.x4.shared.b16 {%0,%1,%2,%3}, [%4];"
        : "=r"(r[0]), "=r"(r[1]), "=r"(r[2]), "=r"(r[3]) : "r"(addr));
}

// ---------------- setup ----------------
__global__ void setup_kernel(const float* __restrict__ extr,
                             const float* __restrict__ w1,
                             const float* __restrict__ w2) {
    int tid = threadIdx.x;
    if (tid < 16) g_cnt[tid] = 0;
    if (tid >= 64 && tid < 72) {
        const float* m = extr + (tid - 64) * 16;
        float inv[16];
        inv[0]  =  m[5]*m[10]*m[15] - m[5]*m[11]*m[14] - m[9]*m[6]*m[15] + m[9]*m[7]*m[14] + m[13]*m[6]*m[11] - m[13]*m[7]*m[10];
        inv[4]  = -m[4]*m[10]*m[15] + m[4]*m[11]*m[14] + m[8]*m[6]*m[15] - m[8]*m[7]*m[14] - m[12]*m[6]*m[11] + m[12]*m[7]*m[10];
        inv[8]  =  m[4]*m[9]*m[15]  - m[4]*m[11]*m[13] - m[8]*m[5]*m[15] + m[8]*m[7]*m[13] + m[12]*m[5]*m[11] - m[12]*m[7]*m[9];
        inv[12] = -m[4]*m[9]*m[14]  + m[4]*m[10]*m[13] + m[8]*m[5]*m[14] - m[8]*m[6]*m[13] - m[12]*m[5]*m[10] + m[12]*m[6]*m[9];
        inv[1]  = -m[1]*m[10]*m[15] + m[1]*m[11]*m[14] + m[9]*m[2]*m[15] - m[9]*m[3]*m[14] - m[13]*m[2]*m[11] + m[13]*m[3]*m[10];
        inv[5]  =  m[0]*m[10]*m[15] - m[0]*m[11]*m[14] - m[8]*m[2]*m[15] + m[8]*m[3]*m[14] + m[12]*m[2]*m[11] - m[12]*m[3]*m[10];
        inv[9]  = -m[0]*m[9]*m[15]  + m[0]*m[11]*m[13] + m[8]*m[1]*m[15] - m[8]*m[3]*m[13] - m[12]*m[1]*m[11] + m[12]*m[3]*m[9];
        inv[13] =  m[0]*m[9]*m[14]  - m[0]*m[10]*m[13] - m[8]*m[1]*m[14] + m[8]*m[2]*m[13] + m[12]*m[1]*m[10] - m[12]*m[2]*m[9];
        inv[2]  =  m[1]*m[6]*m[15]  - m[1]*m[7]*m[14]  - m[5]*m[2]*m[15] + m[5]*m[3]*m[14] + m[13]*m[2]*m[7]  - m[13]*m[3]*m[6];
        inv[6]  = -m[0]*m[6]*m[15]  + m[0]*m[7]*m[14]  + m[4]*m[2]*m[15] - m[4]*m[3]*m[14] - m[12]*m[2]*m[7]  + m[12]*m[3]*m[6];
        inv[10] =  m[0]*m[5]*m[15]  - m[0]*m[7]*m[13]  - m[4]*m[1]*m[15] + m[4]*m[3]*m[13] + m[12]*m[1]*m[7]  - m[12]*m[3]*m[5];
        inv[14] = -m[0]*m[5]*m[14]  + m[0]*m[6]*m[13]  + m[4]*m[1]*m[14] - m[4]*m[2]*m[13] - m[12]*m[1]*m[6]  + m[12]*m[2]*m[5];
        inv[3]  = -m[1]*m[6]*m[11]  + m[1]*m[7]*m[10]  + m[5]*m[2]*m[11] - m[5]*m[3]*m[10] - m[9]*m[2]*m[7]   + m[9]*m[3]*m[6];
        inv[7]  =  m[0]*m[6]*m[11]  - m[0]*m[7]*m[10]  - m[4]*m[2]*m[11] + m[4]*m[3]*m[10] + m[8]*m[2]*m[7]   - m[8]*m[3]*m[6];
        inv[11] = -m[0]*m[5]*m[11]  + m[0]*m[7]*m[9]   + m[4]*m[1]*m[11] - m[4]*m[3]*m[9]  - m[8]*m[1]*m[7]   + m[8]*m[3]*m[5];
        inv[15] =  m[0]*m[5]*m[10]  - m[0]*m[6]*m[9]   - m[4]*m[1]*m[10] + m[4]*m[2]*m[9]  + m[8]*m[1]*m[6]   - m[8]*m[2]*m[5];
        float det = m[0]*inv[0] + m[1]*inv[4] + m[2]*inv[8] + m[3]*inv[12];
        float rd = 1.0f / det;
        for (int n = 0; n < 16; n++) g_w2c[(tid - 64) * 16 + n] = inv[n] * rd;
    }
    // W layout: [conv][coh][tap][col32][64ci] fp16 with 16B-chunk XOR swizzle.
    for (int i = tid; i < 73728; i += blockDim.x) {
        int c = i / 36864;
        int r = i - c * 36864;
        int tap = r >> 12;
        int q = r & 4095;
        int co = q >> 6, ci = q & 63;
        int coh = co >> 5, col = co & 31;
        int chunk = 2 * (ci >> 4) + ((ci >> 3) & 1);
        int dst = ((c * 2 + coh) * 9 + tap) * 2048 + col * 64 +
                  ((chunk ^ (col & 7)) << 3) + (ci & 7);
        g_wB[dst] = __float2half_rn((c ? w2 : w1)[(co * 64 + ci) * 9 + tap]);
    }
}

// ---------------- phase 1: projection + mask counts ----------------
__global__ void proj_kernel(const float* __restrict__ means,
                            const float* __restrict__ intrinsics) {
    int pi = blockIdx.y;
    int b = pi / 6, q = pi - b * 6;
    int j = c_pj[q], k = c_pk[q];
    int slot = (k < j) ? 0 : 1;
    int img = b * 4 + j;
    int pix = blockIdx.x * 256 + threadIdx.x;

    const float* m = means + ((long)img * HW + pix) * 3;
    float X = m[0], Y = m[1], Z = m[2];
    const float* w = g_w2c + (b * 4 + k) * 16;
    float c0 = w[0]*X + w[1]*Y + w[2]*Z  + w[3];
    float c1 = w[4]*X + w[5]*Y + w[6]*Z  + w[7];
    float c2 = w[8]*X + w[9]*Y + w[10]*Z + w[11];
    float dz = c2 + 1e-8f;
    float u0 = c0 / dz, u1 = c1 / dz, u2 = c2 / dz;
    const float* K = intrinsics + (b * 4 + k) * 9;
    float nx = K[0]*u0 + K[1]*u1 + K[2]*u2;
    float ny = K[3]*u0 + K[4]*u1 + K[5]*u2;
    bool mask = (nx >= 0.f) && (nx < 1.f) && (ny >= 0.f) && (ny < 1.f) && (c2 > 1e-8f);
    int px = (int)floorf(nx * 256.f);
    int py = (int)floorf(ny * 256.f);
    px = min(max(px, 0), 255);
    py = min(max(py, 0), 255);
    g_idx[(img * 2 + slot) * HW + pix] = mask ? (py * 256 + px) : -1;
    unsigned bal = __ballot_sync(0xFFFFFFFFu, mask);
    if ((threadIdx.x & 31) == 0)
        atomicAdd(&g_cnt[img * 2 + slot], __popc(bal));
}

// ---------------- phase 2: weighted fusion -> NHWC fp16 ----------
__global__ void fuse_kernel(const float* __restrict__ feats) {
    const int img = blockIdx.y;
    const int j = img & 3;
    const int tid = threadIdx.x;
    const int pxl = tid & 63;
    const int chunk = tid >> 6;
    const int pix = (blockIdx.x << 6) + pxl;

    float s0 = 0.f, s1 = 0.f;
    int i0 = -1, i1 = -1;
    if (j > 0) {
        s0 = 0.1f * (float)g_cnt[img * 2 + 0] * (1.0f / 65536.f);
        i0 = g_idx[(img * 2 + 0) * HW + pix];
    }
    if (j < 3) {
        s1 = 0.1f * (float)g_cnt[img * 2 + 1] * (1.0f / 65536.f);
        i1 = g_idx[(img * 2 + 1) * HW + pix];
    }
    float rnorm = 1.f / (1.f + s0 + s1);

    const float4* sp = reinterpret_cast<const float4*>(feats + ((long)img * HW + pix) * 64 + (chunk << 4));
    float4 r[4];
#pragma unroll
    for (int q = 0; q < 4; q++) r[q] = sp[q];
    if (i0 >= 0) {
        const float4* gp = reinterpret_cast<const float4*>(feats + ((long)(img - 1) * HW + i0) * 64 + (chunk << 4));
#pragma unroll
        for (int q = 0; q < 4; q++) {
            float4 g = gp[q];
            r[q].x += s0 * g.x; r[q].y += s0 * g.y; r[q].z += s0 * g.z; r[q].w += s0 * g.w;
        }
    }
    if (i1 >= 0) {
        const float4* gp = reinterpret_cast<const float4*>(feats + ((long)(img + 1) * HW + i1) * 64 + (chunk << 4));
#pragma unroll
        for (int q = 0; q < 4; q++) {
            float4 g = gp[q];
            r[q].x += s1 * g.x; r[q].y += s1 * g.y; r[q].z += s1 * g.z; r[q].w += s1 * g.w;
        }
    }
    uint4 u0, u1;
    u0.x = f22h(r[0].x * rnorm, r[0].y * rnorm);
    u0.y = f22h(r[0].z * rnorm, r[0].w * rnorm);
    u0.z = f22h(r[1].x * rnorm, r[1].y * rnorm);
    u0.w = f22h(r[1].z * rnorm, r[1].w * rnorm);
    u1.x = f22h(r[2].x * rnorm, r[2].y * rnorm);
    u1.y = f22h(r[2].z * rnorm, r[2].w * rnorm);
    u1.z = f22h(r[3].x * rnorm, r[3].y * rnorm);
    u1.w = f22h(r[3].z * rnorm, r[3].w * rnorm);
    uint4* op = reinterpret_cast<uint4*>(g_fused + ((long)img * HW + pix) * 64 + (chunk << 4));
    op[0] = u0;
    op[1] = u1;
}

// ---------------- conv: fp16 mma + ldmatrix, row walk, 2 CTAs/SM ----------
// CTA = (img, xhalf, coh, y-seg). 256 threads = 4 px-groups x 2 co-groups.
// Warp tile 32px x 16co. Strip = 130px x 64ci fp16. smem 70.3 KB.
#define GELU(v) (0.5f * (v) * (1.0f + erff((v) * 0.70710678118654752f)))
#define XSTRH 8320   // halfwords per X buffer (130 * 64)

#define CONV_BODY(PH, STEPV) do {                                              \
    const int step_ = (STEPV);                                                 \
    { /* prefetch input row y0+step_ into slot (step_+1)&1 */                  \
        int rn = y0 + step_;                                                   \
        int okr = (rn < 256) ? 1 : 0;                                          \
        const char* rowp = (const char*)inp + ((long)img * 256 + min(rn, 255)) * 32768; \
        uint32_t dstb = Xb + (uint32_t)(((step_ + 1) & 1) * (XSTRH * 2));      \
        for (int i = tid; i < 1040; i += 256) {                                \
            int p = i >> 3, c = i & 7;                                         \
            int gx = x0 + p - 1;                                               \
            int ok = (okr && (unsigned)gx < 256u) ? 16 : 0;                    \
            const char* src = rowp + (uint32_t)min(max(gx, 0), 255) * 128u + (uint32_t)c * 16u; \
            uint32_t dst = dstb + (uint32_t)p * 128u + (uint32_t)((c ^ (p & 7)) << 4); \
            asm volatile("cp.async.cg.shared.global [%0], [%1], 16, %2;"       \
                         :: "r"(dst), "l"(src), "r"(ok));                      \
        }                                                                      \
        asm volatile("cp.async.commit_group;" ::: "memory");                   \
    }                                                                          \
    asm volatile("cp.async.wait_group 1;" ::: "memory");                       \
    __syncthreads();                                                           \
    {                                                                          \
        const uint32_t XbufB = Xb + (uint32_t)((step_ & 1) * (XSTRH * 2));     \
        uint32_t laneA[3][2];                                                  \
        _Pragma("unroll")                                                      \
        for (int dxm = 0; dxm < 3; dxm++)                                      \
            _Pragma("unroll")                                                  \
            for (int mt = 0; mt < 2; mt++) {                                   \
                const int px = pb + mt * 16 + dxm + r15;                       \
                laneA[dxm][mt] = (XbufB + (uint32_t)px * 128u +                \
                                  (uint32_t)((px & 7) << 4)) ^ hb16;           \
            }                                                                  \
        _Pragma("unroll")                                                      \
        for (int k16 = 0; k16 < 4; k16++) {                                    \
            const uint32_t kx = (uint32_t)(k16 << 5);                          \
            uint32_t aM[3][2][4];                                              \
            _Pragma("unroll")                                                  \
            for (int dxm = 0; dxm < 3; dxm++)                                  \
                _Pragma("unroll")                                              \
                for (int mt = 0; mt < 2; mt++)                                 \
                    ldsm4(aM[dxm][mt], laneA[dxm][mt] ^ kx);                   \
            _Pragma("unroll")                                                  \
            for (int tr = 0; tr < 3; tr++) {                                   \
                const int S = ((PH) + 1 - tr + 3) % 3;                         \
                if (tr == 0 || step_ >= tr) {                                  \
                    _Pragma("unroll")                                          \
                    for (int dxm = 0; dxm < 3; dxm++) {                        \
                        uint32_t bb[4];                                        \
                        ldsm4(bb, laneW[tr * 3 + dxm] ^ kx);                   \
                        uint32_t b0[2] = {bb[0], bb[2]};                       \
                        uint32_t b1[2] = {bb[1], bb[3]};                       \
                        _Pragma("unroll")                                      \
                        for (int mt = 0; mt < 2; mt++) {                       \
                            mma_f16(acc[S][mt][0], aM[dxm][mt], b0);           \
                            mma_f16(acc[S][mt][1], aM[dxm][mt], b1);           \
                        }                                                      \
                    }                                                          \
                }                                                              \
            }                                                                  \
        }                                                                      \
    }                                                                          \
    if (step_ >= 2) {                                                          \
        const int E = ((PH) + 2) % 3;                                          \
        const int o = y0 + step_ - 2;                                          \
        _Pragma("unroll")                                                      \
        for (int mt = 0; mt < 2; mt++) {                                       \
            _Pragma("unroll")                                                  \
            for (int h = 0; h < 2; h++) {                                      \
                const int px = x0 + pb + mt * 16 + grp + h * 8;                \
                const long obase = ((long)img * HW + (long)o * 256 + px) * 64 + coh * 32; \
                _Pragma("unroll")                                              \
                for (int nt = 0; nt < 2; nt++) {                               \
                    const int co = coq * 16 + nt * 8 + q4 * 2;                 \
                    float vx = acc[E][mt][nt][h * 2 + 0] + bsm[co];            \
                    float vy = acc[E][mt][nt][h * 2 + 1] + bsm[co + 1];        \
                    if (MODE == 0) {                                           \
                        vx = GELU(vx);                                         \
                        vy = GELU(vy);                                         \
                        *reinterpret_cast<uint32_t*>(g_mid + obase + co) = f22h(vx, vy); \
                    } else {                                                   \
                        float2 v; v.x = vx; v.y = vy;                          \
                        *reinterpret_cast<float2*>(outf + obase + co) = v;     \
                    }                                                          \
                }                                                              \
            }                                                                  \
        }                                                                      \
        _Pragma("unroll")                                                      \
        for (int mt = 0; mt < 2; mt++)                                         \
            _Pragma("unroll")                                                  \
            for (int nt = 0; nt < 2; nt++)                                     \
                _Pragma("unroll")                                              \
                for (int e = 0; e < 4; e++) acc[E][mt][nt][e] = 0.f;           \
    }                                                                          \
    __syncthreads();                                                           \
} while (0)

template <int MODE>
__global__ __launch_bounds__(256, 2) void conv_mma(const float* __restrict__ bias,
                                                   float* __restrict__ d_outp) {
    extern __shared__ char smx[];
    __half* Wsm = reinterpret_cast<__half*>(smx);            // 36,864 B
    __half* Xsm = reinterpret_cast<__half*>(smx + 36864);    // 2 x 16,640 B
    float* bsm = reinterpret_cast<float*>(smx + 36864 + 33280); // 128 B

    const int tid = threadIdx.x;
    const int bx = blockIdx.x;
    const int coh = bx & 1;
    const int r1 = bx >> 1;
    const int seg = r1 % 9;
    const int r2 = r1 / 9;
    const int xh = r2 & 1;
    const int img = r2 >> 1;
    const int y0 = seg * 29;
    const int rows = (seg == 8) ? 24 : 29;
    const int x0 = xh * 128;

    const __half* __restrict__ inp = (MODE == 0) ? g_fused : g_mid;
    float* __restrict__ outf = d_outp;

    {
        const uint4* ws = reinterpret_cast<const uint4*>(g_wB + (MODE * 2 + coh) * 18432);
        uint4* wd = reinterpret_cast<uint4*>(Wsm);
        for (int i = tid; i < 2304; i += 256) wd[i] = ws[i];
        if (tid < 32) bsm[tid] = bias[coh * 32 + tid];
    }

    const uint32_t Xb = smem_u32(Xsm);
    const uint32_t Wb = smem_u32(Wsm);
    const int lane = tid & 31;
    const int wrp = tid >> 5;
    const int grp = lane >> 2, q4 = lane & 3;
    const int pxq = wrp & 3, coq = wrp >> 2;
    const int pb = pxq * 32;
    const int r15 = lane & 15;
    const uint32_t hb16 = (uint32_t)((lane >> 4) << 4);

    // per-lane W ldmatrix bases (one per tap)
    uint32_t laneW[9];
#pragma unroll
    for (int t = 0; t < 9; t++) {
        const int co = coq * 16 + r15;
        laneW[t] = (Wb + (uint32_t)t * 4096u + (uint32_t)co * 128u +
                    (uint32_t)((co & 7) << 4)) ^ hb16;
    }

    float acc[3][2][2][4];
#pragma unroll
    for (int s = 0; s < 3; s++)
#pragma unroll
        for (int mt = 0; mt < 2; mt++)
#pragma unroll
            for (int nt = 0; nt < 2; nt++)
#pragma unroll
                for (int e = 0; e < 4; e++) acc[s][mt][nt][e] = 0.f;

    // prologue: load strip r = y0-1 into buf 0
    {
        int rn = y0 - 1;
        int okr = (rn >= 0) ? 1 : 0;
        const char* rowp = (const char*)inp + ((long)img * 256 + max(rn, 0)) * 32768;
        for (int i = tid; i < 1040; i += 256) {
            int p = i >> 3, c = i & 7;
            int gx = x0 + p - 1;
            int ok = (okr && (unsigned)gx < 256u) ? 16 : 0;
            const char* src = rowp + (uint32_t)min(max(gx, 0), 255) * 128u + (uint32_t)c * 16u;
            uint32_t dst = Xb + (uint32_t)p * 128u + (uint32_t)((c ^ (p & 7)) << 4);
            asm volatile("cp.async.cg.shared.global [%0], [%1], 16, %2;"
                         :: "r"(dst), "l"(src), "r"(ok));
        }
        asm volatile("cp.async.commit_group;" ::: "memory");
    }

    const int T = rows + 2;
    for (int s = 0; s < T; s += 3) {
        CONV_BODY(0, s);
        if (s + 1 < T) CONV_BODY(1, s + 1);
        if (s + 2 < T) CONV_BODY(2, s + 2);
    }
}

// ---------------- launch ----------------
extern "C" void kernel_launch(void* const* d_in, const int* in_sizes, int n_in,
                              void* d_out, int out_size) {
    const float* means      = (const float*)d_in[0];
    const float* gs_feats   = (const float*)d_in[2];
    const float* intrinsics = (const float*)d_in[3];
    const float* extrinsics = (const float*)d_in[4];
    const float* w1 = (const float*)d_in[5];
    const float* b1 = (const float*)d_in[6];
    const float* w2 = (const float*)d_in[7];
    const float* b2 = (const float*)d_in[8];
    float* out = (float*)d_out;

    const int smem = 36864 + 33280 + 128;  // 70,272 B
    cudaFuncSetAttribute(conv_mma<0>, cudaFuncAttributeMaxDynamicSharedMemorySize, smem);
    cudaFuncSetAttribute(conv_mma<1>, cudaFuncAttributeMaxDynamicSharedMemorySize, smem);

    setup_kernel<<<1, 256>>>(extrinsics, w1, w2);
    proj_kernel<<<dim3(256, 12), 256>>>(means, intrinsics);
    fuse_kernel<<<dim3(1024, 8), 256>>>(gs_feats);
    conv_mma<0><<<288, 256, smem>>>(b1, out);
    conv_mma<1><<<288, 256, smem>>>(b2, out);
}

// round 17
// speedup vs baseline: 1.0387x; 1.0387x over previous
#include <cuda_runtime.h>
#include <cuda_fp16.h>
#include <math.h>
#include <stdint.h>

#define HW 65536

// ---------------- device scratch ----------------
__device__ float  g_w2c[8 * 16];
__device__ int    g_idx[16 * HW];
__device__ int    g_cnt[16];
__device__ __half g_wB[2 * 2 * 9 * 32 * 64]; // [conv][coh][tap][col32][64ci] swizzled fp16
__device__ __half g_fused[8ll * HW * 64];    // NHWC fp16
__device__ __half g_mid[8ll * HW * 64];      // NHWC fp16

__constant__ int c_pj[6] = {0, 1, 1, 2, 2, 3};
__constant__ int c_pk[6] = {1, 0, 2, 1, 3, 2};

__device__ __forceinline__ uint32_t smem_u32(const void* p) {
    uint32_t a;
    asm("{ .reg .u64 t; cvta.to.shared.u64 t, %1; cvt.u32.u64 %0, t; }" : "=r"(a) : "l"(p));
    return a;
}
__device__ __forceinline__ uint32_t f22h(float a, float b) {
    __half2 h = __floats2half2_rn(a, b);
    return *reinterpret_cast<uint32_t*>(&h);
}
__device__ __forceinline__ void mma_f16(float* d, const uint32_t* a, const uint32_t* b) {
    asm volatile(
        "mma.sync.aligned.m16n8k16.row.col.f32.f16.f16.f32 "
        "{%0,%1,%2,%3}, {%4,%5,%6,%7}, {%8,%9}, {%0,%1,%2,%3};"
        : "+f"(d[0]), "+f"(d[1]), "+f"(d[2]), "+f"(d[3])
        : "r"(a[0]), "r"(a[1]), "r"(a[2]), "r"(a[3]), "r"(b[0]), "r"(b[1]));
}
__device__ __forceinline__ void ldsm4(uint32_t* r, uint32_t addr) {
    asm volatile("ldmatrix.sync.aligned.m8n8.x4.shared.b16 {%0,%1,%2,%3}, [%4];"
        : "=r"(r[0]), "=r"(r[1]), "=r"(r[2]), "=r"(r[3]) : "r"(addr));
}

// ---------------- setup ----------------
__global__ void setup_kernel(const float* __restrict__ extr,
                             const float* __restrict__ w1,
                             const float* __restrict__ w2) {
    int tid = threadIdx.x;
    if (tid < 16) g_cnt[tid] = 0;
    if (tid >= 64 && tid < 72) {
        const float* m = extr + (tid - 64) * 16;
        float inv[16];
        inv[0]  =  m[5]*m[10]*m[15] - m[5]*m[11]*m[14] - m[9]*m[6]*m[15] + m[9]*m[7]*m[14] + m[13]*m[6]*m[11] - m[13]*m[7]*m[10];
        inv[4]  = -m[4]*m[10]*m[15] + m[4]*m[11]*m[14] + m[8]*m[6]*m[15] - m[8]*m[7]*m[14] - m[12]*m[6]*m[11] + m[12]*m[7]*m[10];
        inv[8]  =  m[4]*m[9]*m[15]  - m[4]*m[11]*m[13] - m[8]*m[5]*m[15] + m[8]*m[7]*m[13] + m[12]*m[5]*m[11] - m[12]*m[7]*m[9];
        inv[12] = -m[4]*m[9]*m[14]  + m[4]*m[10]*m[13] + m[8]*m[5]*m[14] - m[8]*m[6]*m[13] - m[12]*m[5]*m[10] + m[12]*m[6]*m[9];
        inv[1]  = -m[1]*m[10]*m[15] + m[1]*m[11]*m[14] + m[9]*m[2]*m[15] - m[9]*m[3]*m[14] - m[13]*m[2]*m[11] + m[13]*m[3]*m[10];
        inv[5]  =  m[0]*m[10]*m[15] - m[0]*m[11]*m[14] - m[8]*m[2]*m[15] + m[8]*m[3]*m[14] + m[12]*m[2]*m[11] - m[12]*m[3]*m[10];
        inv[9]  = -m[0]*m[9]*m[15]  + m[0]*m[11]*m[13] + m[8]*m[1]*m[15] - m[8]*m[3]*m[13] - m[12]*m[1]*m[11] + m[12]*m[3]*m[9];
        inv[13] =  m[0]*m[9]*m[14]  - m[0]*m[10]*m[13] - m[8]*m[1]*m[14] + m[8]*m[2]*m[13] + m[12]*m[1]*m[10] - m[12]*m[2]*m[9];
        inv[2]  =  m[1]*m[6]*m[15]  - m[1]*m[7]*m[14]  - m[5]*m[2]*m[15] + m[5]*m[3]*m[14] + m[13]*m[2]*m[7]  - m[13]*m[3]*m[6];
        inv[6]  = -m[0]*m[6]*m[15]  + m[0]*m[7]*m[14]  + m[4]*m[2]*m[15] - m[4]*m[3]*m[14] - m[12]*m[2]*m[7]  + m[12]*m[3]*m[6];
        inv[10] =  m[0]*m[5]*m[15]  - m[0]*m[7]*m[13]  - m[4]*m[1]*m[15] + m[4]*m[3]*m[13] + m[12]*m[1]*m[7]  - m[12]*m[3]*m[5];
        inv[14] = -m[0]*m[5]*m[14]  + m[0]*m[6]*m[13]  + m[4]*m[1]*m[14] - m[4]*m[2]*m[13] - m[12]*m[1]*m[6]  + m[12]*m[2]*m[5];
        inv[3]  = -m[1]*m[6]*m[11]  + m[1]*m[7]*m[10]  + m[5]*m[2]*m[11] - m[5]*m[3]*m[10] - m[9]*m[2]*m[7]   + m[9]*m[3]*m[6];
        inv[7]  =  m[0]*m[6]*m[11]  - m[0]*m[7]*m[10]  - m[4]*m[2]*m[11] + m[4]*m[3]*m[10] + m[8]*m[2]*m[7]   - m[8]*m[3]*m[6];
        inv[11] = -m[0]*m[5]*m[11]  + m[0]*m[7]*m[9]   + m[4]*m[1]*m[11] - m[4]*m[3]*m[9]  - m[8]*m[1]*m[7]   + m[8]*m[3]*m[5];
        inv[15] =  m[0]*m[5]*m[10]  - m[0]*m[6]*m[9]   - m[4]*m[1]*m[10] + m[4]*m[2]*m[9]  + m[8]*m[1]*m[6]   - m[8]*m[2]*m[5];
        float det = m[0]*inv[0] + m[1]*inv[4] + m[2]*inv[8] + m[3]*inv[12];
        float rd = 1.0f / det;
        for (int n = 0; n < 16; n++) g_w2c[(tid - 64) * 16 + n] = inv[n] * rd;
    }
    // W layout: [conv][coh][tap][col32][64ci] fp16 with 16B-chunk XOR swizzle.
    for (int i = tid; i < 73728; i += blockDim.x) {
        int c = i / 36864;
        int r = i - c * 36864;
        int tap = r >> 12;
        int q = r & 4095;
        int co = q >> 6, ci = q & 63;
        int coh = co >> 5, col = co & 31;
        int chunk = 2 * (ci >> 4) + ((ci >> 3) & 1);
        int dst = ((c * 2 + coh) * 9 + tap) * 2048 + col * 64 +
                  ((chunk ^ (col & 7)) << 3) + (ci & 7);
        g_wB[dst] = __float2half_rn((c ? w2 : w1)[(co * 64 + ci) * 9 + tap]);
    }
}

// ---------------- phase 1: projection + mask counts ----------------
__global__ void proj_kernel(const float* __restrict__ means,
                            const float* __restrict__ intrinsics) {
    int pi = blockIdx.y;
    int b = pi / 6, q = pi - b * 6;
    int j = c_pj[q], k = c_pk[q];
    int slot = (k < j) ? 0 : 1;
    int img = b * 4 + j;
    int pix = blockIdx.x * 256 + threadIdx.x;

    const float* m = means + ((long)img * HW + pix) * 3;
    float X = m[0], Y = m[1], Z = m[2];
    const float* w = g_w2c + (b * 4 + k) * 16;
    float c0 = w[0]*X + w[1]*Y + w[2]*Z  + w[3];
    float c1 = w[4]*X + w[5]*Y + w[6]*Z  + w[7];
    float c2 = w[8]*X + w[9]*Y + w[10]*Z + w[11];
    float dz = c2 + 1e-8f;
    float u0 = c0 / dz, u1 = c1 / dz, u2 = c2 / dz;
    const float* K = intrinsics + (b * 4 + k) * 9;
    float nx = K[0]*u0 + K[1]*u1 + K[2]*u2;
    float ny = K[3]*u0 + K[4]*u1 + K[5]*u2;
    bool mask = (nx >= 0.f) && (nx < 1.f) && (ny >= 0.f) && (ny < 1.f) && (c2 > 1e-8f);
    int px = (int)floorf(nx * 256.f);
    int py = (int)floorf(ny * 256.f);
    px = min(max(px, 0), 255);
    py = min(max(py, 0), 255);
    g_idx[(img * 2 + slot) * HW + pix] = mask ? (py * 256 + px) : -1;
    unsigned bal = __ballot_sync(0xFFFFFFFFu, mask);
    if ((threadIdx.x & 31) == 0)
        atomicAdd(&g_cnt[img * 2 + slot], __popc(bal));
}

// ---------------- phase 2: weighted fusion -> NHWC fp16 ----------
__global__ void fuse_kernel(const float* __restrict__ feats) {
    const int img = blockIdx.y;
    const int j = img & 3;
    const int tid = threadIdx.x;
    const int pxl = tid & 63;
    const int chunk = tid >> 6;
    const int pix = (blockIdx.x << 6) + pxl;

    float s0 = 0.f, s1 = 0.f;
    int i0 = -1, i1 = -1;
    if (j > 0) {
        s0 = 0.1f * (float)g_cnt[img * 2 + 0] * (1.0f / 65536.f);
        i0 = g_idx[(img * 2 + 0) * HW + pix];
    }
    if (j < 3) {
        s1 = 0.1f * (float)g_cnt[img * 2 + 1] * (1.0f / 65536.f);
        i1 = g_idx[(img * 2 + 1) * HW + pix];
    }
    float rnorm = 1.f / (1.f + s0 + s1);

    const float4* sp = reinterpret_cast<const float4*>(feats + ((long)img * HW + pix) * 64 + (chunk << 4));
    float4 r[4];
#pragma unroll
    for (int q = 0; q < 4; q++) r[q] = sp[q];
    if (i0 >= 0) {
        const float4* gp = reinterpret_cast<const float4*>(feats + ((long)(img - 1) * HW + i0) * 64 + (chunk << 4));
#pragma unroll
        for (int q = 0; q < 4; q++) {
            float4 g = gp[q];
            r[q].x += s0 * g.x; r[q].y += s0 * g.y; r[q].z += s0 * g.z; r[q].w += s0 * g.w;
        }
    }
    if (i1 >= 0) {
        const float4* gp = reinterpret_cast<const float4*>(feats + ((long)(img + 1) * HW + i1) * 64 + (chunk << 4));
#pragma unroll
        for (int q = 0; q < 4; q++) {
            float4 g = gp[q];
            r[q].x += s1 * g.x; r[q].y += s1 * g.y; r[q].z += s1 * g.z; r[q].w += s1 * g.w;
        }
    }
    uint4 u0, u1;
    u0.x = f22h(r[0].x * rnorm, r[0].y * rnorm);
    u0.y = f22h(r[0].z * rnorm, r[0].w * rnorm);
    u0.z = f22h(r[1].x * rnorm, r[1].y * rnorm);
    u0.w = f22h(r[1].z * rnorm, r[1].w * rnorm);
    u1.x = f22h(r[2].x * rnorm, r[2].y * rnorm);
    u1.y = f22h(r[2].z * rnorm, r[2].w * rnorm);
    u1.z = f22h(r[3].x * rnorm, r[3].y * rnorm);
    u1.w = f22h(r[3].z * rnorm, r[3].w * rnorm);
    uint4* op = reinterpret_cast<uint4*>(g_fused + ((long)img * HW + pix) * 64 + (chunk << 4));
    op[0] = u0;
    op[1] = u1;
}

// ---------------- conv: fp16 mma + ldmatrix, W in registers ----------------
// CTA = (img, xhalf, coh, y-seg). 256 threads = 4 px-groups x 2 co-groups.
// Warp tile 32px x 16co. Weights: 144 regs/thread, loaded once.
#define GELU(v) (0.5f * (v) * (1.0f + erff((v) * 0.70710678118654752f)))
#define XSTRH 8320   // halfwords per X buffer (130 * 64)

#define CONV_BODY(PH, STEPV) do {                                              \
    const int step_ = (STEPV);                                                 \
    { /* prefetch input row y0+step_ into slot (step_+1)&1 */                  \
        int rn = y0 + step_;                                                   \
        int okr = (rn < 256) ? 1 : 0;                                          \
        const char* rowp = (const char*)inp + ((long)img * 256 + min(rn, 255)) * 32768; \
        uint32_t dstb = Xb + (uint32_t)(((step_ + 1) & 1) * (XSTRH * 2));      \
        for (int i = tid; i < 1040; i += 256) {                                \
            int p = i >> 3, c = i & 7;                                         \
            int gx = x0 + p - 1;                                               \
            int ok = (okr && (unsigned)gx < 256u) ? 16 : 0;                    \
            const char* src = rowp + (uint32_t)min(max(gx, 0), 255) * 128u + (uint32_t)c * 16u; \
            uint32_t dst = dstb + (uint32_t)p * 128u + (uint32_t)((c ^ (p & 7)) << 4); \
            asm volatile("cp.async.cg.shared.global [%0], [%1], 16, %2;"       \
                         :: "r"(dst), "l"(src), "r"(ok));                      \
        }                                                                      \
        asm volatile("cp.async.commit_group;" ::: "memory");                   \
    }                                                                          \
    asm volatile("cp.async.wait_group 1;" ::: "memory");                       \
    __syncthreads();                                                           \
    {                                                                          \
        const uint32_t XbufB = Xb + (uint32_t)((step_ & 1) * (XSTRH * 2));     \
        uint32_t laneA[3][2];                                                  \
        _Pragma("unroll")                                                      \
        for (int dxm = 0; dxm < 3; dxm++)                                      \
            _Pragma("unroll")                                                  \
            for (int mt = 0; mt < 2; mt++) {                                   \
                const int px = pb + mt * 16 + dxm + r15;                       \
                laneA[dxm][mt] = (XbufB + (uint32_t)px * 128u +                \
                                  (uint32_t)((px & 7) << 4)) ^ hb16;           \
            }                                                                  \
        _Pragma("unroll")                                                      \
        for (int k16 = 0; k16 < 4; k16++) {                                    \
            const uint32_t kx = (uint32_t)(k16 << 5);                          \
            uint32_t aM[3][2][4];                                              \
            _Pragma("unroll")                                                  \
            for (int dxm = 0; dxm < 3; dxm++)                                  \
                _Pragma("unroll")                                              \
                for (int mt = 0; mt < 2; mt++)                                 \
                    ldsm4(aM[dxm][mt], laneA[dxm][mt] ^ kx);                   \
            _Pragma("unroll")                                                  \
            for (int tr = 0; tr < 3; tr++) {                                   \
                const int S = ((PH) + 1 - tr + 3) % 3;                         \
                if (tr == 0 || step_ >= tr) {                                  \
                    _Pragma("unroll")                                          \
                    for (int dxm = 0; dxm < 3; dxm++) {                        \
                        const uint32_t* wr = wreg[tr * 3 + dxm][k16];          \
                        const uint32_t b0[2] = {wr[0], wr[2]};                 \
                        const uint32_t b1[2] = {wr[1], wr[3]};                 \
                        _Pragma("unroll")                                      \
                        for (int mt = 0; mt < 2; mt++) {                       \
                            mma_f16(acc[S][mt][0], aM[dxm][mt], b0);           \
                            mma_f16(acc[S][mt][1], aM[dxm][mt], b1);           \
                        }                                                      \
                    }                                                          \
                }                                                              \
            }                                                                  \
        }                                                                      \
    }                                                                          \
    if (step_ >= 2) {                                                          \
        const int E = ((PH) + 2) % 3;                                          \
        const int o = y0 + step_ - 2;                                          \
        _Pragma("unroll")                                                      \
        for (int mt = 0; mt < 2; mt++) {                                       \
            _Pragma("unroll")                                                  \
            for (int h = 0; h < 2; h++) {                                      \
                const int px = x0 + pb + mt * 16 + grp + h * 8;                \
                const long obase = ((long)img * HW + (long)o * 256 + px) * 64 + coh * 32; \
                _Pragma("unroll")                                              \
                for (int nt = 0; nt < 2; nt++) {                               \
                    const int co = coq * 16 + nt * 8 + q4 * 2;                 \
                    float vx = acc[E][mt][nt][h * 2 + 0] + bsm[co];            \
                    float vy = acc[E][mt][nt][h * 2 + 1] + bsm[co + 1];        \
                    if (MODE == 0) {                                           \
                        vx = GELU(vx);                                         \
                        vy = GELU(vy);                                         \
                        *reinterpret_cast<uint32_t*>(g_mid + obase + co) = f22h(vx, vy); \
                    } else {                                                   \
                        float2 v; v.x = vx; v.y = vy;                          \
                        *reinterpret_cast<float2*>(outf + obase + co) = v;     \
                    }                                                          \
                }                                                              \
            }                                                                  \
        }                                                                      \
        _Pragma("unroll")                                                      \
        for (int mt = 0; mt < 2; mt++)                                         \
            _Pragma("unroll")                                                  \
            for (int nt = 0; nt < 2; nt++)                                     \
                _Pragma("unroll")                                              \
                for (int e = 0; e < 4; e++) acc[E][mt][nt][e] = 0.f;           \
    }                                                                          \
    __syncthreads();                                                           \
} while (0)

template <int MODE>
__global__ __launch_bounds__(256, 1) void conv_mma(const float* __restrict__ bias,
                                                   float* __restrict__ d_outp) {
    extern __shared__ char smx[];
    __half* Wsm = reinterpret_cast<__half*>(smx);            // 36,864 B
    __half* Xsm = reinterpret_cast<__half*>(smx + 36864);    // 2 x 16,640 B
    float* bsm = reinterpret_cast<float*>(smx + 36864 + 33280); // 128 B

    const int tid = threadIdx.x;
    const int bx = blockIdx.x;
    const int coh = bx & 1;
    const int r1 = bx >> 1;
    const int seg = r1 % 9;
    const int r2 = r1 / 9;
    const int xh = r2 & 1;
    const int img = r2 >> 1;
    const int y0 = seg * 29;
    const int rows = (seg == 8) ? 24 : 29;
    const int x0 = xh * 128;

    const __half* __restrict__ inp = (MODE == 0) ? g_fused : g_mid;
    float* __restrict__ outf = d_outp;

    {
        const uint4* ws = reinterpret_cast<const uint4*>(g_wB + (MODE * 2 + coh) * 18432);
        uint4* wd = reinterpret_cast<uint4*>(Wsm);
        for (int i = tid; i < 2304; i += 256) wd[i] = ws[i];
        if (tid < 32) bsm[tid] = bias[coh * 32 + tid];
    }

    const uint32_t Xb = smem_u32(Xsm);
    const uint32_t Wb = smem_u32(Wsm);
    const int lane = tid & 31;
    const int wrp = tid >> 5;
    const int grp = lane >> 2, q4 = lane & 3;
    const int pxq = wrp & 3, coq = wrp >> 2;
    const int pb = pxq * 32;
    const int r15 = lane & 15;
    const uint32_t hb16 = (uint32_t)((lane >> 4) << 4);

    __syncthreads();

    // Load all weight fragments into registers (once).
    uint32_t wreg[9][4][4];
    {
        const int co = coq * 16 + r15;
        const uint32_t wl = (Wb + (uint32_t)co * 128u + (uint32_t)((co & 7) << 4)) ^ hb16;
#pragma unroll
        for (int t = 0; t < 9; t++)
#pragma unroll
            for (int k = 0; k < 4; k++)
                ldsm4(wreg[t][k], (wl + (uint32_t)t * 4096u) ^ (uint32_t)(k << 5));
    }

    float acc[3][2][2][4];
#pragma unroll
    for (int s = 0; s < 3; s++)
#pragma unroll
        for (int mt = 0; mt < 2; mt++)
#pragma unroll
            for (int nt = 0; nt < 2; nt++)
#pragma unroll
                for (int e = 0; e < 4; e++) acc[s][mt][nt][e] = 0.f;

    // prologue: load strip r = y0-1 into buf 0
    {
        int rn = y0 - 1;
        int okr = (rn >= 0) ? 1 : 0;
        const char* rowp = (const char*)inp + ((long)img * 256 + max(rn, 0)) * 32768;
        for (int i = tid; i < 1040; i += 256) {
            int p = i >> 3, c = i & 7;
            int gx = x0 + p - 1;
            int ok = (okr && (unsigned)gx < 256u) ? 16 : 0;
            const char* src = rowp + (uint32_t)min(max(gx, 0), 255) * 128u + (uint32_t)c * 16u;
            uint32_t dst = Xb + (uint32_t)p * 128u + (uint32_t)((c ^ (p & 7)) << 4);
            asm volatile("cp.async.cg.shared.global [%0], [%1], 16, %2;"
                         :: "r"(dst), "l"(src), "r"(ok));
        }
        asm volatile("cp.async.commit_group;" ::: "memory");
    }

    const int T = rows + 2;
    for (int s = 0; s < T; s += 3) {
        CONV_BODY(0, s);
        if (s + 1 < T) CONV_BODY(1, s + 1);
        if (s + 2 < T) CONV_BODY(2, s + 2);
    }
}

// ---------------- launch ----------------
extern "C" void kernel_launch(void* const* d_in, const int* in_sizes, int n_in,
                              void* d_out, int out_size) {
    const float* means      = (const float*)d_in[0];
    const float* gs_feats   = (const float*)d_in[2];
    const float* intrinsics = (const float*)d_in[3];
    const float* extrinsics = (const float*)d_in[4];
    const float* w1 = (const float*)d_in[5];
    const float* b1 = (const float*)d_in[6];
    const float* w2 = (const float*)d_in[7];
    const float* b2 = (const float*)d_in[8];
    float* out = (float*)d_out;

    const int smem = 36864 + 33280 + 128;  // 70,272 B
    cudaFuncSetAttribute(conv_mma<0>, cudaFuncAttributeMaxDynamicSharedMemorySize, smem);
    cudaFuncSetAttribute(conv_mma<1>, cudaFuncAttributeMaxDynamicSharedMemorySize, smem);

    setup_kernel<<<1, 256>>>(extrinsics, w1, w2);
    proj_kernel<<<dim3(256, 12), 256>>>(means, intrinsics);
    fuse_kernel<<<dim3(1024, 8), 256>>>(gs_feats);
    conv_mma<0><<<288, 256, smem>>>(b1, out);
    conv_mma<1><<<288, 256, smem>>>(b2, out);
}